// round 2
// baseline (speedup 1.0000x reference)
#include <cuda_runtime.h>
#include <cuda_bf16.h>
#include <math.h>

// ---------------- problem constants ----------------
#define BATCH 2
#define C_IN 192
#define C3 576            // 3*C
#define HW 65536          // 256*256
#define IMG 256
#define HEADS 6
#define CH 32
#define WS 8
#define NTOK 64           // WS*WS
#define NWIN 2048         // BATCH * 32 * 32

// intermediates as device globals (no allocation allowed)
__device__ float g_qkv1[(size_t)BATCH * C3 * HW];                       // after 1x1 conv (b, ch3, h, w)
__device__ float g_win[(size_t)3 * NWIN * HEADS * CH * NTOK];           // window layout (z, win, head, c, tok)
__device__ float g_att[(size_t)BATCH * C_IN * HW];                      // attention output, (b, c, h, w)

// ---------------------------------------------------------------------------
// K1/K4: SGEMM  Y[o,p] = sum_c W[o,c] * X[c,p] (+bias), K=192 fixed.
// Tile: 96(o) x 128(p) x 8(k); 256 threads, 6x8 microtile per thread.
// M must be a multiple of 96 (576 and 192 both are).
// ---------------------------------------------------------------------------
__global__ __launch_bounds__(256) void k_gemm192(
    const float* __restrict__ Wt, const float* __restrict__ Xall,
    float* __restrict__ Yall, const float* __restrict__ bias, int M)
{
    const float* X = Xall + (size_t)blockIdx.z * C_IN * HW;
    float* Y = Yall + (size_t)blockIdx.z * (size_t)M * HW;
    const int oTile = blockIdx.y * 96;
    const int pTile = blockIdx.x * 128;

    __shared__ float Ws[8][96];
    __shared__ float Xs[8][128];

    const int tid = threadIdx.x;
    const int to = tid >> 4;    // 0..15
    const int tp = tid & 15;    // 0..15

    float acc[6][8];
#pragma unroll
    for (int i = 0; i < 6; i++)
#pragma unroll
        for (int j = 0; j < 8; j++) acc[i][j] = 0.f;

    for (int k0 = 0; k0 < 192; k0 += 8) {
#pragma unroll
        for (int it = 0; it < 3; it++) {           // 96*8 = 768 elems
            int e = tid + it * 256;
            int r = e >> 3, c = e & 7;
            Ws[c][r] = Wt[(size_t)(oTile + r) * 192 + k0 + c];
        }
#pragma unroll
        for (int it = 0; it < 4; it++) {           // 8*128 = 1024 elems
            int e = tid + it * 256;
            int r = e >> 7, cc = e & 127;
            Xs[r][cc] = X[(size_t)(k0 + r) * HW + pTile + cc];
        }
        __syncthreads();
#pragma unroll
        for (int kk = 0; kk < 8; kk++) {
            float a[6], b[8];
#pragma unroll
            for (int i = 0; i < 6; i++) a[i] = Ws[kk][to + 16 * i];
#pragma unroll
            for (int j = 0; j < 8; j++) b[j] = Xs[kk][tp + 16 * j];
#pragma unroll
            for (int i = 0; i < 6; i++)
#pragma unroll
                for (int j = 0; j < 8; j++) acc[i][j] = fmaf(a[i], b[j], acc[i][j]);
        }
        __syncthreads();
    }

#pragma unroll
    for (int i = 0; i < 6; i++) {
        int o = oTile + to + 16 * i;
        float bs = bias ? bias[o] : 0.f;
#pragma unroll
        for (int j = 0; j < 8; j++)
            Y[(size_t)o * HW + pTile + tp + 16 * j] = acc[i][j] + bs;
    }
}

// ---------------------------------------------------------------------------
// K2: depthwise 3x3 (zero pad 1) + scatter into window layout
//   dst(z, win, head, c, tok) where win=b*1024+h1*32+w1, tok=(h%8)*8+(w%8)
// ---------------------------------------------------------------------------
__global__ __launch_bounds__(256) void k_dwconv(
    const float* __restrict__ in, const float* __restrict__ wd,
    float* __restrict__ outWin)
{
    const int plane = blockIdx.z;            // b*576 + ch3
    const int b = plane / C3, ch3 = plane - b * C3;
    const int x0 = blockIdx.x * 32, y0 = blockIdx.y * 8;

    __shared__ float sm[10][34];
    const float* P = in + (size_t)plane * HW;
    const int tx = threadIdx.x, ty = threadIdx.y;
    const int lt = ty * 32 + tx;

    for (int e = lt; e < 340; e += 256) {
        int r = e / 34, cc = e - r * 34;
        int gy = y0 - 1 + r, gx = x0 - 1 + cc;
        float v = 0.f;
        if (gy >= 0 && gy < IMG && gx >= 0 && gx < IMG) v = P[gy * IMG + gx];
        sm[r][cc] = v;
    }
    __syncthreads();

    const float* wp = wd + ch3 * 9;
    float s = wp[0] * sm[ty + 0][tx + 0] + wp[1] * sm[ty + 0][tx + 1] + wp[2] * sm[ty + 0][tx + 2]
            + wp[3] * sm[ty + 1][tx + 0] + wp[4] * sm[ty + 1][tx + 1] + wp[5] * sm[ty + 1][tx + 2]
            + wp[6] * sm[ty + 2][tx + 0] + wp[7] * sm[ty + 2][tx + 1] + wp[8] * sm[ty + 2][tx + 2];

    const int h = y0 + ty, w = x0 + tx;
    const int z = ch3 / 192;
    const int head = (ch3 % 192) >> 5;
    const int c = ch3 & 31;
    const int win = b * 1024 + (h >> 3) * 32 + (w >> 3);
    const int tok = ((h & 7) << 3) + (w & 7);
    size_t dst = ((((size_t)z * NWIN + win) * HEADS + head) * CH + c) * NTOK + tok;
    outWin[dst] = s;
}

// ---------------------------------------------------------------------------
// K3: per (window, head) attention tile. 256 threads.
//   q,k,v : 32 x 64.  l2norm rows of q,k; A = qk^T * temp; softmax rows;
//   O = A v ; gate = gelu(v @ mlp_w^T + b); out = O * gate -> (b,c,h,w)
// stride-65 smem padding for conflict-free strided row reads.
// ---------------------------------------------------------------------------
__global__ __launch_bounds__(256) void k_attn(
    const float* __restrict__ winBuf, const float* __restrict__ temperature,
    const float* __restrict__ mlp_w, const float* __restrict__ mlp_b,
    float* __restrict__ out)
{
    const int blk = blockIdx.x;          // winId*6 + head
    const int winId = blk / 6, head = blk - winId * 6;

    __shared__ float qs[32 * 65];
    __shared__ float ks[32 * 65];
    __shared__ float vs[32 * 65];
    __shared__ float As[32 * 33];
    __shared__ float mws[64 * 65];
    __shared__ float mbs[64];

    const int tid = threadIdx.x;
    const size_t base = (size_t)blk * (CH * NTOK);
    const size_t zs = (size_t)NWIN * HEADS * CH * NTOK;

    for (int e = tid; e < CH * NTOK; e += 256) {
        int r = e >> 6, c = e & 63;
        qs[r * 65 + c] = winBuf[base + e];
        ks[r * 65 + c] = winBuf[zs + base + e];
        vs[r * 65 + c] = winBuf[2 * zs + base + e];
    }
    for (int e = tid; e < 4096; e += 256)
        mws[(e >> 6) * 65 + (e & 63)] = mlp_w[e];
    if (tid < 64) mbs[tid] = mlp_b[tid];
    __syncthreads();

    // ---- l2 normalize rows of q and k (64 rows, 4 threads/row) ----
    {
        int r = tid >> 2;
        int sub = tid & 3;
        float* rowp = (r < 32) ? (qs + r * 65) : (ks + (r - 32) * 65);
        float ss = 0.f;
#pragma unroll
        for (int i = 0; i < 16; i++) { float v = rowp[sub * 16 + i]; ss += v * v; }
        ss += __shfl_xor_sync(0xffffffffu, ss, 1);
        ss += __shfl_xor_sync(0xffffffffu, ss, 2);
        float inv = 1.0f / fmaxf(sqrtf(ss), 1e-12f);
#pragma unroll
        for (int i = 0; i < 16; i++) rowp[sub * 16 + i] *= inv;
    }
    __syncthreads();

    const float temp = temperature[head];

    // ---- A = q k^T * temp : 32x32, 4 outputs/thread ----
    {
        int c = tid >> 3, d0 = (tid & 7) * 4;
        float a0 = 0.f, a1 = 0.f, a2 = 0.f, a3 = 0.f;
#pragma unroll
        for (int x = 0; x < 64; x++) {
            float qv = qs[c * 65 + x];
            a0 = fmaf(qv, ks[(d0 + 0) * 65 + x], a0);
            a1 = fmaf(qv, ks[(d0 + 1) * 65 + x], a1);
            a2 = fmaf(qv, ks[(d0 + 2) * 65 + x], a2);
            a3 = fmaf(qv, ks[(d0 + 3) * 65 + x], a3);
        }
        As[c * 33 + d0 + 0] = a0 * temp;
        As[c * 33 + d0 + 1] = a1 * temp;
        As[c * 33 + d0 + 2] = a2 * temp;
        As[c * 33 + d0 + 3] = a3 * temp;
    }
    __syncthreads();

    // ---- softmax over rows of A (32 wide), 8 threads/row ----
    {
        int r = tid >> 3, j0 = (tid & 7) * 4;
        float v[4];
#pragma unroll
        for (int i = 0; i < 4; i++) v[i] = As[r * 33 + j0 + i];
        float m = fmaxf(fmaxf(v[0], v[1]), fmaxf(v[2], v[3]));
        m = fmaxf(m, __shfl_xor_sync(0xffffffffu, m, 1));
        m = fmaxf(m, __shfl_xor_sync(0xffffffffu, m, 2));
        m = fmaxf(m, __shfl_xor_sync(0xffffffffu, m, 4));
        float s = 0.f;
#pragma unroll
        for (int i = 0; i < 4; i++) { v[i] = __expf(v[i] - m); s += v[i]; }
        s += __shfl_xor_sync(0xffffffffu, s, 1);
        s += __shfl_xor_sync(0xffffffffu, s, 2);
        s += __shfl_xor_sync(0xffffffffu, s, 4);
        float inv = 1.0f / s;
#pragma unroll
        for (int i = 0; i < 4; i++) As[r * 33 + j0 + i] = v[i] * inv;
    }
    __syncthreads();

    // ---- O = A @ v, gate = gelu(v @ mlp_w^T + b), write O*gate ----
    {
        int c = tid >> 3, x0 = (tid & 7) * 8;
        float o[8], g[8];
#pragma unroll
        for (int xx = 0; xx < 8; xx++) { o[xx] = 0.f; g[xx] = mbs[x0 + xx]; }

#pragma unroll
        for (int d = 0; d < 32; d++) {
            float a = As[c * 33 + d];
#pragma unroll
            for (int xx = 0; xx < 8; xx++)
                o[xx] = fmaf(a, vs[d * 65 + x0 + xx], o[xx]);
        }
#pragma unroll
        for (int j = 0; j < 64; j++) {
            float vv = vs[c * 65 + j];
#pragma unroll
            for (int xx = 0; xx < 8; xx++)
                g[xx] = fmaf(vv, mws[(x0 + xx) * 65 + j], g[xx]);
        }

        const int b = winId >> 10, rem = winId & 1023;
        const int h1 = rem >> 5, w1 = rem & 31;
        const int hh = x0 >> 3;                 // all 8 tokens share row hh
        const int h = h1 * 8 + hh;
        size_t outBase = (((size_t)b * C_IN + head * CH + c) * IMG + h) * IMG + w1 * 8;
#pragma unroll
        for (int xx = 0; xx < 8; xx++) {
            float x = g[xx];
            float ge = 0.5f * x * (1.0f + erff(x * 0.70710678118654752f));
            out[outBase + xx] = o[xx] * ge;
        }
    }
}

// ---------------------------------------------------------------------------
extern "C" void kernel_launch(void* const* d_in, const int* in_sizes, int n_in,
                              void* d_out, int out_size)
{
    const float* x           = (const float*)d_in[0];
    const float* w_qkv       = (const float*)d_in[1];
    const float* w_dw        = (const float*)d_in[2];
    const float* temperature = (const float*)d_in[3];
    const float* mlp_w       = (const float*)d_in[4];
    const float* mlp_b       = (const float*)d_in[5];
    const float* proj_w      = (const float*)d_in[6];
    const float* proj_b      = (const float*)d_in[7];
    float* out = (float*)d_out;

    float *qkv1, *winb, *att;
    cudaGetSymbolAddress((void**)&qkv1, g_qkv1);
    cudaGetSymbolAddress((void**)&winb, g_win);
    cudaGetSymbolAddress((void**)&att, g_att);

    // K1: qkv = x @ w_qkv^T  (M=576)
    k_gemm192<<<dim3(HW / 128, C3 / 96, BATCH), 256>>>(w_qkv, x, qkv1, nullptr, C3);
    // K2: depthwise 3x3 + window transpose
    k_dwconv<<<dim3(IMG / 32, IMG / 8, BATCH * C3), dim3(32, 8)>>>(qkv1, w_dw, winb);
    // K3: per-(window,head) attention
    k_attn<<<NWIN * HEADS, 256>>>(winb, temperature, mlp_w, mlp_b, att);
    // K4: projection (M=192, with bias)
    k_gemm192<<<dim3(HW / 128, C_IN / 96, BATCH), 256>>>(proj_w, att, out, proj_b, C_IN);
}